// round 15
// baseline (speedup 1.0000x reference)
#include <cuda_runtime.h>
#include <cuda_bf16.h>
#include <stdint.h>

// Problem constants
#define BATCH 256
#define M 128
#define NIMG 100
#define NP 104          // 13 * 8
#define D 768
#define ITERS 50

// Full-batch GEMM staging (per buffer, swizzled bf16, 128B rows)
#define XHI_OFF 0u
#define XLO_OFF 16384u
#define YHI_OFF 32768u
#define BUF_BYTES 46080u
#define NBUF 4
#define DSM_GEMM (NBUF * 46080 + 1024)

#define QP_STRIDE 68    // 64 partial cols + 4 pad floats

#define SWZ(o) ((o) ^ (((o) >> 3) & 0x70))

#define BAR_SYNC(id)   asm volatile("bar.sync %0, 512;"   :: "r"(id) : "memory")
#define BAR_ARRIVE(id) asm volatile("bar.arrive %0, 512;" :: "r"(id) : "memory")

// A stored as fragment blob in ipot geometry:
// g_A[((b*8 + w)*13 + t)*128 + lane*4 + e]
__device__ __align__(16) float g_A[BATCH * 8 * 13 * 128];
__device__ float g_ot[BATCH];
__device__ int   g_isU8;

// ---------------------------------------------------------------------------
// Helpers
// ---------------------------------------------------------------------------
__device__ __forceinline__ uint32_t smem_u32(const void* p) {
    uint32_t a;
    asm("{ .reg .u64 t; cvta.to.shared.u64 t, %1; cvt.u32.u64 %0, t; }"
        : "=r"(a) : "l"(p));
    return a;
}
__device__ __forceinline__ void ldsm4(uint32_t addr, uint32_t* r) {
    asm volatile("ldmatrix.sync.aligned.m8n8.x4.shared.b16 {%0,%1,%2,%3}, [%4];"
                 : "=r"(r[0]), "=r"(r[1]), "=r"(r[2]), "=r"(r[3]) : "r"(addr));
}
__device__ __forceinline__ void mma_bf16(float* d, const uint32_t* a,
                                         uint32_t b0, uint32_t b1) {
    asm volatile(
        "mma.sync.aligned.m16n8k16.row.col.f32.bf16.bf16.f32 "
        "{%0,%1,%2,%3},{%4,%5,%6,%7},{%8,%9},{%0,%1,%2,%3};"
        : "+f"(d[0]), "+f"(d[1]), "+f"(d[2]), "+f"(d[3])
        : "r"(a[0]), "r"(a[1]), "r"(a[2]), "r"(a[3]), "r"(b0), "r"(b1));
}
__device__ __forceinline__ void split2(float a, float b, uint32_t& hi, uint32_t& lo) {
    asm("cvt.rn.bf16x2.f32 %0, %1, %2;" : "=r"(hi) : "f"(b), "f"(a));
    float ah = __uint_as_float(hi << 16);
    float bh = __uint_as_float(hi & 0xffff0000u);
    float la = a - ah, lb = b - bh;
    asm("cvt.rn.bf16x2.f32 %0, %1, %2;" : "=r"(lo) : "f"(lb), "f"(la));
}
__device__ __forceinline__ uint32_t cvt2(float a, float b) {
    uint32_t hi;
    asm("cvt.rn.bf16x2.f32 %0, %1, %2;" : "=r"(hi) : "f"(b), "f"(a));
    return hi;
}

__device__ __forceinline__ float conv_store_xl(char* bb, uint32_t sw0, uint32_t sw1,
                                               float4 f0, float4 f1,
                                               float4 f2, float4 f3) {
    float ss = f0.x*f0.x + f0.y*f0.y + f0.z*f0.z + f0.w*f0.w
             + f1.x*f1.x + f1.y*f1.y + f1.z*f1.z + f1.w*f1.w
             + f2.x*f2.x + f2.y*f2.y + f2.z*f2.z + f2.w*f2.w
             + f3.x*f3.x + f3.y*f3.y + f3.z*f3.z + f3.w*f3.w;
    uint4 hi, lo;
    split2(f0.x, f0.y, hi.x, lo.x);
    split2(f0.z, f0.w, hi.y, lo.y);
    split2(f1.x, f1.y, hi.z, lo.z);
    split2(f1.z, f1.w, hi.w, lo.w);
    *(uint4*)(bb + XHI_OFF + sw0) = hi;
    *(uint4*)(bb + XLO_OFF + sw0) = lo;
    split2(f2.x, f2.y, hi.x, lo.x);
    split2(f2.z, f2.w, hi.y, lo.y);
    split2(f3.x, f3.y, hi.z, lo.z);
    split2(f3.z, f3.w, hi.w, lo.w);
    *(uint4*)(bb + XHI_OFF + sw1) = hi;
    *(uint4*)(bb + XLO_OFF + sw1) = lo;
    return ss;
}
__device__ __forceinline__ float conv_store_yh(char* bb, uint32_t sw0, uint32_t sw1,
                                               float4 f0, float4 f1,
                                               float4 f2, float4 f3) {
    float ss = f0.x*f0.x + f0.y*f0.y + f0.z*f0.z + f0.w*f0.w
             + f1.x*f1.x + f1.y*f1.y + f1.z*f1.z + f1.w*f1.w
             + f2.x*f2.x + f2.y*f2.y + f2.z*f2.z + f2.w*f2.w
             + f3.x*f3.x + f3.y*f3.y + f3.z*f3.z + f3.w*f3.w;
    uint4 hi;
    hi.x = cvt2(f0.x, f0.y); hi.y = cvt2(f0.z, f0.w);
    hi.z = cvt2(f1.x, f1.y); hi.w = cvt2(f1.z, f1.w);
    *(uint4*)(bb + YHI_OFF + sw0) = hi;
    hi.x = cvt2(f2.x, f2.y); hi.y = cvt2(f2.z, f2.w);
    hi.z = cvt2(f3.x, f3.y); hi.w = cvt2(f3.z, f3.w);
    *(uint4*)(bb + YHI_OFF + sw1) = hi;
    return ss;
}

__global__ void k_nop() {}

// ---------------------------------------------------------------------------
// Pad-dtype detect (uint8-bool vs int32)
// ---------------------------------------------------------------------------
__global__ void __launch_bounds__(512) k_detect(const unsigned char* __restrict__ tp,
                                                const unsigned char* __restrict__ ip) {
    __shared__ int sflag;
    int tid = threadIdx.x;
    if (tid == 0) sflag = 0;
    __syncthreads();
    uint32_t acc = 0;
    const uint4* t4 = (const uint4*)tp;
    for (int i = tid; i < 2048; i += 512) {
        uint4 v = t4[i];
        acc |= (v.x | v.y | v.z | v.w) & 0xFFFFFF00u;
    }
    const uint4* i4 = (const uint4*)ip;
    for (int i = tid; i < 1600; i += 512) {
        uint4 v = i4[i];
        acc |= (v.x | v.y | v.z | v.w) & 0xFFFFFF00u;
    }
    uint32_t any = __ballot_sync(0xffffffffu, acc != 0);
    if ((tid & 31) == 0 && any) atomicOr(&sflag, 1);
    __syncthreads();
    if (tid == 0) g_isU8 = sflag;
}

// ---------------------------------------------------------------------------
// Warp-specialized full-batch GEMM (unchanged from R14): grid 256, 512 thr,
// 4-deep buffers, producers 8-15, consumers 0-7.
// ---------------------------------------------------------------------------
__global__ void __launch_bounds__(512, 1) k_gemm(const float* __restrict__ seq,
                                                 const unsigned char* __restrict__ tp,
                                                 const unsigned char* __restrict__ ip) {
    extern __shared__ __align__(16) char dsm[];
    __shared__ float pSq[928];
    __shared__ float sNxi[M], sNyi[NP];
    __shared__ float sXm[M], sYm[NP];

    const int b = blockIdx.x, tid = threadIdx.x;
    const int lane = tid & 31, w = tid >> 5;

    uint32_t rawb = smem_u32(dsm);
    uint32_t sb = (rawb + 1023u) & ~1023u;
    char* sbuf = dsm + (sb - rawb);

    const int u8 = g_isU8;
    if (tid < M) {
        int pad = u8 ? (tp[b * M + tid] != 0) : (((const int*)tp)[b * M + tid] != 0);
        sXm[tid] = pad ? 1e4f : 0.f;
    } else if (tid < M + NP) {
        int n = tid - M;
        int pad = (n >= NIMG) ? 1
                : (u8 ? (ip[b * NIMG + n] != 0) : (((const int*)ip)[b * NIMG + n] != 0));
        sYm[n] = pad ? 1e4f : 0.f;
    }
    __syncthreads();

    const float* seqb = seq + (size_t)b * 228 * D;

    if (w >= 8) {
        const int p = tid - 256;
        const int prow = p >> 2, pseg = p & 3;
        const float* px0 = seqb + (size_t)prow * D + pseg * 16;
        const float* px1 = px0 + (size_t)64 * D;
        const uint32_t xs00 = SWZ((uint32_t)(prow * 128 + pseg * 32));
        const uint32_t xs01 = SWZ((uint32_t)(prow * 128 + pseg * 32 + 16));
        const uint32_t xs10 = SWZ((uint32_t)((prow + 64) * 128 + pseg * 32));
        const uint32_t xs11 = SWZ((uint32_t)((prow + 64) * 128 + pseg * 32 + 16));
        const float* py0 = seqb + (size_t)(128 + prow) * D + pseg * 16;
        const int hasY1 = p < 144;
        const int zeroY1 = (p >= 144) && (p < 160);
        const float* py1 = py0 + (size_t)64 * D;
        const uint32_t ys00 = SWZ((uint32_t)(prow * 128 + pseg * 32));
        const uint32_t ys01 = SWZ((uint32_t)(prow * 128 + pseg * 32 + 16));
        const uint32_t ys10 = SWZ((uint32_t)((prow + 64) * 128 + pseg * 32));
        const uint32_t ys11 = SWZ((uint32_t)((prow + 64) * 128 + pseg * 32 + 16));

        if (zeroY1) {
            uint4 z = make_uint4(0u, 0u, 0u, 0u);
#pragma unroll
            for (int i = 0; i < NBUF; i++) {
                *(uint4*)(sbuf + i * BUF_BYTES + YHI_OFF + ys10) = z;
                *(uint4*)(sbuf + i * BUF_BYTES + YHI_OFF + ys11) = z;
            }
        }

        float nx0a = 0.f, nx1a = 0.f, ny0a = 0.f, ny1a = 0.f;
        for (int c = 0; c < 12; c++) {
            if (c >= NBUF) BAR_SYNC(5 + (c & 3));
            char* bb = sbuf + (uint32_t)(c & 3) * BUF_BYTES;
            const int co = c * 16;
            const float4* q;
            float4 x00, x01, x02, x03, x10, x11, x12, x13;
            float4 y00, y01, y02, y03, y10, y11, y12, y13;
            q = (const float4*)px0 + co; x00 = q[0]; x01 = q[1]; x02 = q[2]; x03 = q[3];
            q = (const float4*)px1 + co; x10 = q[0]; x11 = q[1]; x12 = q[2]; x13 = q[3];
            q = (const float4*)py0 + co; y00 = q[0]; y01 = q[1]; y02 = q[2]; y03 = q[3];
            if (hasY1) {
                q = (const float4*)py1 + co; y10 = q[0]; y11 = q[1]; y12 = q[2]; y13 = q[3];
            }
            nx0a += conv_store_xl(bb, xs00, xs01, x00, x01, x02, x03);
            nx1a += conv_store_xl(bb, xs10, xs11, x10, x11, x12, x13);
            ny0a += conv_store_yh(bb, ys00, ys01, y00, y01, y02, y03);
            if (hasY1)
                ny1a += conv_store_yh(bb, ys10, ys11, y10, y11, y12, y13);
            asm volatile("membar.cta;" ::: "memory");
            BAR_ARRIVE(1 + (c & 3));
        }
        pSq[p] = nx0a;
        pSq[p + 256] = nx1a;
        pSq[512 + p] = ny0a;
        if (p < 160) pSq[512 + p + 256] = ny1a;
        __syncthreads();
        if (tid - 256 < M) {
            int m = tid - 256;
            float ss = pSq[4 * m] + pSq[4 * m + 1] + pSq[4 * m + 2] + pSq[4 * m + 3];
            sNxi[m] = 1.f / fmaxf(sqrtf(ss), 1e-5f);
        }
        __syncthreads();
    } else {
        const int g = lane >> 2, q2 = lane & 3;
        const int j8 = lane >> 3, sub = lane & 7;
        const uint32_t arow_off = (uint32_t)((16 * w + ((j8 & 1) << 3) + sub) * 128);
        const int acol = (j8 >> 1) * 8;
        const int bcol = j8 * 8;

        float acc[52];
#pragma unroll
        for (int i = 0; i < 52; i++) acc[i] = 0.f;

        for (int c = 0; c < 12; c++) {
            BAR_SYNC(1 + (c & 3));
            uint32_t bbase = sb + (uint32_t)(c & 3) * BUF_BYTES;
#pragma unroll
            for (int k0 = 0; k0 < 64; k0 += 32) {
                uint32_t ah0[4], ah1[4], al0[4], al1[4];
                uint32_t offA0 = SWZ(arow_off + (uint32_t)((k0 + acol) * 2));
                uint32_t offA1 = SWZ(arow_off + (uint32_t)((k0 + 16 + acol) * 2));
                ldsm4(bbase + XHI_OFF + offA0, ah0);
                ldsm4(bbase + XHI_OFF + offA1, ah1);
                ldsm4(bbase + XLO_OFF + offA0, al0);
                ldsm4(bbase + XLO_OFF + offA1, al1);
#pragma unroll
                for (int t = 0; t < 13; t++) {
                    uint32_t offB = SWZ((uint32_t)((8 * t + sub) * 128 + (k0 + bcol) * 2));
                    uint32_t bh[4];
                    ldsm4(bbase + YHI_OFF + offB, bh);
                    float* d = &acc[t * 4];
                    mma_bf16(d, ah0, bh[0], bh[1]);
                    mma_bf16(d, al0, bh[0], bh[1]);
                    mma_bf16(d, ah1, bh[2], bh[3]);
                    mma_bf16(d, al1, bh[2], bh[3]);
                }
            }
            if (c < 12 - NBUF) BAR_ARRIVE(5 + (c & 3));
        }
        __syncthreads();
        if (tid < M + NP && tid >= M) {
            int n = tid - M;
            float ss = pSq[512 + 4 * n] + pSq[512 + 4 * n + 1]
                     + pSq[512 + 4 * n + 2] + pSq[512 + 4 * n + 3];
            sNyi[n] = 1.f / fmaxf(sqrtf(ss), 1e-5f);
        }
        __syncthreads();

        const int m0 = 16 * w + g, m1 = m0 + 8;
        const float xm0 = sXm[m0], xm1 = sXm[m1];
        const float nx0 = sNxi[m0], nx1 = sNxi[m1];
        float* gAout = g_A + ((size_t)(b * 8 + w) * 13) * 128;
#pragma unroll
        for (int t = 0; t < 13; t++) {
            int n0 = 8 * t + 2 * q2, n1 = n0 + 1;
            float ny0 = sNyi[n0], ny1 = sNyi[n1];
            float ym0 = sYm[n0],  ym1 = sYm[n1];
            float4 a;
            a.x = (xm0 > 0.f || ym0 > 0.f) ? 0.f
                : __expf(2.f * (acc[t * 4 + 0] * nx0 * ny0 - 1.f));
            a.y = (xm0 > 0.f || ym1 > 0.f) ? 0.f
                : __expf(2.f * (acc[t * 4 + 1] * nx0 * ny1 - 1.f));
            a.z = (xm1 > 0.f || ym0 > 0.f) ? 0.f
                : __expf(2.f * (acc[t * 4 + 2] * nx1 * ny0 - 1.f));
            a.w = (xm1 > 0.f || ym1 > 0.f) ? 0.f
                : __expf(2.f * (acc[t * 4 + 3] * nx1 * ny1 - 1.f));
            *(float4*)(gAout + t * 128 + lane * 4) = a;
        }
        return;
    }
}

// ---------------------------------------------------------------------------
// IPOT kernel R15: A AND Q register-resident (52+52). No dl[] cache —
// sDelta re-loaded (broadcast LDS.64). A-blob loads gmem->regs directly
// (coalesced). smem: only sQP (28KB) + small. 256 threads, 2 CTAs/SM.
// ---------------------------------------------------------------------------
__global__ void __launch_bounds__(256, 2) k_ipot(const unsigned char* __restrict__ tp,
                                                 const unsigned char* __restrict__ ip) {
    __shared__ __align__(16) float sQP[NP * QP_STRIDE];
    __shared__ float sXm[M], sYm[NP];
    __shared__ __align__(8) float sDelta[NP];
    __shared__ float sRed[8];
    __shared__ int sCx, sCy;

    const int b = blockIdx.x, tid = threadIdx.x;
    const int lane = tid & 31, w = tid >> 5;
    const int g = lane >> 2, q2 = lane & 3;
    const int col = 8 * w + g;

    if (tid == 0) { sCx = 0; sCy = 0; }
    __syncthreads();
    const int u8 = g_isU8;
    if (tid < M) {
        int pad = u8 ? (tp[b * M + tid] != 0) : (((const int*)tp)[b * M + tid] != 0);
        sXm[tid] = pad ? 1e4f : 0.f;
        if (pad) atomicAdd(&sCx, 1);
    }
    if (tid < NP) {
        int pad = (tid >= NIMG) ? 1
                : (u8 ? (ip[b * NIMG + tid] != 0) : (((const int*)ip)[b * NIMG + tid] != 0));
        sYm[tid] = pad ? 1e4f : 0.f;
        if (pad && tid < NIMG) atomicAdd(&sCy, 1);
    }
    __syncthreads();

    // A blob gmem -> registers (coalesced float4 per t)
    float Ar[52], Qr[52];
    const float4* gA4 = (const float4*)(g_A + ((size_t)(b * 8 + w) * 13) * 128) + lane;
#pragma unroll
    for (int t = 0; t < 13; t++) {
        float4 a = gA4[t * 32];
        Ar[t * 4 + 0] = a.x; Qr[t * 4 + 0] = a.x;
        Ar[t * 4 + 1] = a.y; Qr[t * 4 + 1] = a.y;
        Ar[t * 4 + 2] = a.z; Qr[t * 4 + 2] = a.z;
        Ar[t * 4 + 3] = a.w; Qr[t * 4 + 3] = a.w;
    }

    const int m0 = 16 * w + g;
    const float xm0 = sXm[m0], xm1 = sXm[m0 + 8];
    const float xl = (float)(M - sCx), yl = (float)(NIMG - sCy);

    float sig0 = xm0 > 0.f ? 0.f : 1.f / xl;
    float sig1 = xm1 > 0.f ? 0.f : 1.f / xl;

#pragma unroll
    for (int t = 0; t < 13; t++) {
        int n0 = 8 * t + 2 * q2;
        sQP[n0 * QP_STRIDE + col]       = Qr[t * 4 + 0] * sig0 + Qr[t * 4 + 2] * sig1;
        sQP[(n0 + 1) * QP_STRIDE + col] = Qr[t * 4 + 1] * sig0 + Qr[t * 4 + 3] * sig1;
    }
    __syncthreads();

    float ot = 0.f;
#pragma unroll 1
    for (int it = 0; it < ITERS; it++) {
        // delta[n]: sum 64 partials (16 LDS.128)
        if (tid < NP) {
            const float4* rp = (const float4*)&sQP[tid * QP_STRIDE];
            float4 r0 = rp[0], r1 = rp[1], r2 = rp[2], r3 = rp[3];
#pragma unroll
            for (int j = 4; j < 16; j += 4) {
                float4 v0 = rp[j], v1 = rp[j + 1], v2 = rp[j + 2], v3 = rp[j + 3];
                r0.x += v0.x; r0.y += v0.y; r0.z += v0.z; r0.w += v0.w;
                r1.x += v1.x; r1.y += v1.y; r1.z += v1.z; r1.w += v1.w;
                r2.x += v2.x; r2.y += v2.y; r2.z += v2.z; r2.w += v2.w;
                r3.x += v3.x; r3.y += v3.y; r3.z += v3.z; r3.w += v3.w;
            }
            float qs = (r0.x + r0.y + r0.z + r0.w) + (r1.x + r1.y + r1.z + r1.w)
                     + (r2.x + r2.y + r2.z + r2.w) + (r3.x + r3.y + r3.z + r3.w);
            sDelta[tid] = __fdividef(1.f, yl * qs + sYm[tid]);
        }
        __syncthreads();

        // r[m] = sum_n delta[n]*Q[n,m]; sigma warp-local (xor 1,2).
        // sDelta loaded fresh (broadcast) — no dl[] register cache.
        float p0 = 0.f, p1 = 0.f;
#pragma unroll
        for (int t = 0; t < 13; t++) {
            float2 d = *(const float2*)&sDelta[8 * t + 2 * q2];
            p0 += d.x * Qr[t * 4 + 0] + d.y * Qr[t * 4 + 1];
            p1 += d.x * Qr[t * 4 + 2] + d.y * Qr[t * 4 + 3];
        }
        p0 += __shfl_xor_sync(0xffffffffu, p0, 1);
        p0 += __shfl_xor_sync(0xffffffffu, p0, 2);
        p1 += __shfl_xor_sync(0xffffffffu, p1, 1);
        p1 += __shfl_xor_sync(0xffffffffu, p1, 2);
        sig0 = __fdividef(1.f, xl * p0 + xm0);
        sig1 = __fdividef(1.f, xl * p1 + xm1);

        if (it < ITERS - 1) {
#pragma unroll
            for (int t = 0; t < 13; t++) {
                float2 d = *(const float2*)&sDelta[8 * t + 2 * q2];
                float q0 = Ar[t * 4 + 0] * Qr[t * 4 + 0] * (d.x * sig0);
                float q1 = Ar[t * 4 + 1] * Qr[t * 4 + 1] * (d.y * sig0);
                float q2v = Ar[t * 4 + 2] * Qr[t * 4 + 2] * (d.x * sig1);
                float q3 = Ar[t * 4 + 3] * Qr[t * 4 + 3] * (d.y * sig1);
                Qr[t * 4 + 0] = q0; Qr[t * 4 + 1] = q1;
                Qr[t * 4 + 2] = q2v; Qr[t * 4 + 3] = q3;
                int n0 = 8 * t + 2 * q2;
                sQP[n0 * QP_STRIDE + col]       = q0 * sig0 + q2v * sig1;
                sQP[(n0 + 1) * QP_STRIDE + col] = q1 * sig0 + q3 * sig1;
            }
        } else {
#pragma unroll
            for (int t = 0; t < 13; t++) {
                float2 d = *(const float2*)&sDelta[8 * t + 2 * q2];
                float a0 = Ar[t * 4 + 0], a1 = Ar[t * 4 + 1];
                float a2 = Ar[t * 4 + 2], a3 = Ar[t * 4 + 3];
                if (a0 > 0.f) ot += (-0.5f * __logf(a0)) * Qr[t * 4 + 0] * d.x * sig0;
                if (a1 > 0.f) ot += (-0.5f * __logf(a1)) * Qr[t * 4 + 1] * d.y * sig0;
                if (a2 > 0.f) ot += (-0.5f * __logf(a2)) * Qr[t * 4 + 2] * d.x * sig1;
                if (a3 > 0.f) ot += (-0.5f * __logf(a3)) * Qr[t * 4 + 3] * d.y * sig1;
            }
        }
        __syncthreads();
    }

    ot += __shfl_xor_sync(0xffffffffu, ot, 16);
    ot += __shfl_xor_sync(0xffffffffu, ot, 8);
    ot += __shfl_xor_sync(0xffffffffu, ot, 4);
    ot += __shfl_xor_sync(0xffffffffu, ot, 2);
    ot += __shfl_xor_sync(0xffffffffu, ot, 1);
    if (lane == 0) sRed[w] = ot;
    __syncthreads();
    if (tid == 0) {
        float sum = 0.f;
#pragma unroll
        for (int ww = 0; ww < 8; ww++) sum += sRed[ww];
        g_ot[b] = sum;
    }
}

// ---------------------------------------------------------------------------
// Final signed batch reduction -> scalar loss.
// ---------------------------------------------------------------------------
__global__ void k_final(const int* __restrict__ isc, float* __restrict__ out) {
    int t = threadIdx.x;
    __shared__ float sRed[8];
    float v = g_ot[t];
    float s = (isc[t] == 1) ? v : -v;
    s += __shfl_xor_sync(0xffffffffu, s, 16);
    s += __shfl_xor_sync(0xffffffffu, s, 8);
    s += __shfl_xor_sync(0xffffffffu, s, 4);
    s += __shfl_xor_sync(0xffffffffu, s, 2);
    s += __shfl_xor_sync(0xffffffffu, s, 1);
    if ((t & 31) == 0) sRed[t >> 5] = s;
    __syncthreads();
    if (t == 0) {
        float tot = 0.f;
#pragma unroll
        for (int w = 0; w < 8; w++) tot += sRed[w];
        out[0] = tot / (float)BATCH;
    }
}

// ---------------------------------------------------------------------------
extern "C" void kernel_launch(void* const* d_in, const int* in_sizes, int n_in,
                              void* d_out, int out_size) {
    const float* seq = (const float*)d_in[0];
    const unsigned char* tp = (const unsigned char*)d_in[3];
    const unsigned char* ip = (const unsigned char*)d_in[4];
    const int* isc = (const int*)d_in[5];
    float* out = (float*)d_out;

    cudaFuncSetAttribute(k_gemm, cudaFuncAttributeMaxDynamicSharedMemorySize,
                         DSM_GEMM);

    k_detect<<<1, 512>>>(tp, ip);
    k_nop<<<1, 32>>>();   // spacer: k_ipot is profiled launch #4
    k_gemm<<<BATCH, 512, DSM_GEMM>>>(seq, tp, ip);
    k_ipot<<<BATCH, 256>>>(tp, ip);
    k_final<<<1, 256>>>(isc, out);
}

// round 16
// speedup vs baseline: 1.1500x; 1.1500x over previous
#include <cuda_runtime.h>
#include <cuda_bf16.h>
#include <stdint.h>

// Problem constants
#define BATCH 256
#define M 128
#define NIMG 100
#define NP 104          // 13 * 8
#define D 768
#define ITERS 50

// Full-batch GEMM staging (per buffer, swizzled bf16, 128B rows)
#define XHI_OFF 0u
#define XLO_OFF 16384u
#define YHI_OFF 32768u
#define BUF_BYTES 46080u
#define NBUF 4
#define DSM_GEMM (NBUF * 46080 + 1024)

#define QP_STRIDE 68    // 64 partial cols + 4 pad floats

#define SWZ(o) ((o) ^ (((o) >> 3) & 0x70))

#define BAR_SYNC(id)   asm volatile("bar.sync %0, 512;"   :: "r"(id) : "memory")
#define BAR_ARRIVE(id) asm volatile("bar.arrive %0, 512;" :: "r"(id) : "memory")

// A stored as fragment blob in ipot geometry:
// g_A[((b*8 + w)*13 + t)*128 + lane*4 + e]
__device__ __align__(16) float g_A[BATCH * 8 * 13 * 128];
__device__ float g_ot[BATCH];
__device__ int   g_isU8;

// ---------------------------------------------------------------------------
// Helpers
// ---------------------------------------------------------------------------
__device__ __forceinline__ uint32_t smem_u32(const void* p) {
    uint32_t a;
    asm("{ .reg .u64 t; cvta.to.shared.u64 t, %1; cvt.u32.u64 %0, t; }"
        : "=r"(a) : "l"(p));
    return a;
}
__device__ __forceinline__ void ldsm4(uint32_t addr, uint32_t* r) {
    asm volatile("ldmatrix.sync.aligned.m8n8.x4.shared.b16 {%0,%1,%2,%3}, [%4];"
                 : "=r"(r[0]), "=r"(r[1]), "=r"(r[2]), "=r"(r[3]) : "r"(addr));
}
__device__ __forceinline__ void mma_bf16(float* d, const uint32_t* a,
                                         uint32_t b0, uint32_t b1) {
    asm volatile(
        "mma.sync.aligned.m16n8k16.row.col.f32.bf16.bf16.f32 "
        "{%0,%1,%2,%3},{%4,%5,%6,%7},{%8,%9},{%0,%1,%2,%3};"
        : "+f"(d[0]), "+f"(d[1]), "+f"(d[2]), "+f"(d[3])
        : "r"(a[0]), "r"(a[1]), "r"(a[2]), "r"(a[3]), "r"(b0), "r"(b1));
}
__device__ __forceinline__ void split2(float a, float b, uint32_t& hi, uint32_t& lo) {
    asm("cvt.rn.bf16x2.f32 %0, %1, %2;" : "=r"(hi) : "f"(b), "f"(a));
    float ah = __uint_as_float(hi << 16);
    float bh = __uint_as_float(hi & 0xffff0000u);
    float la = a - ah, lb = b - bh;
    asm("cvt.rn.bf16x2.f32 %0, %1, %2;" : "=r"(lo) : "f"(lb), "f"(la));
}
__device__ __forceinline__ uint32_t cvt2(float a, float b) {
    uint32_t hi;
    asm("cvt.rn.bf16x2.f32 %0, %1, %2;" : "=r"(hi) : "f"(b), "f"(a));
    return hi;
}

__device__ __forceinline__ float conv_store_xl(char* bb, uint32_t sw0, uint32_t sw1,
                                               float4 f0, float4 f1,
                                               float4 f2, float4 f3) {
    float ss = f0.x*f0.x + f0.y*f0.y + f0.z*f0.z + f0.w*f0.w
             + f1.x*f1.x + f1.y*f1.y + f1.z*f1.z + f1.w*f1.w
             + f2.x*f2.x + f2.y*f2.y + f2.z*f2.z + f2.w*f2.w
             + f3.x*f3.x + f3.y*f3.y + f3.z*f3.z + f3.w*f3.w;
    uint4 hi, lo;
    split2(f0.x, f0.y, hi.x, lo.x);
    split2(f0.z, f0.w, hi.y, lo.y);
    split2(f1.x, f1.y, hi.z, lo.z);
    split2(f1.z, f1.w, hi.w, lo.w);
    *(uint4*)(bb + XHI_OFF + sw0) = hi;
    *(uint4*)(bb + XLO_OFF + sw0) = lo;
    split2(f2.x, f2.y, hi.x, lo.x);
    split2(f2.z, f2.w, hi.y, lo.y);
    split2(f3.x, f3.y, hi.z, lo.z);
    split2(f3.z, f3.w, hi.w, lo.w);
    *(uint4*)(bb + XHI_OFF + sw1) = hi;
    *(uint4*)(bb + XLO_OFF + sw1) = lo;
    return ss;
}
__device__ __forceinline__ float conv_store_yh(char* bb, uint32_t sw0, uint32_t sw1,
                                               float4 f0, float4 f1,
                                               float4 f2, float4 f3) {
    float ss = f0.x*f0.x + f0.y*f0.y + f0.z*f0.z + f0.w*f0.w
             + f1.x*f1.x + f1.y*f1.y + f1.z*f1.z + f1.w*f1.w
             + f2.x*f2.x + f2.y*f2.y + f2.z*f2.z + f2.w*f2.w
             + f3.x*f3.x + f3.y*f3.y + f3.z*f3.z + f3.w*f3.w;
    uint4 hi;
    hi.x = cvt2(f0.x, f0.y); hi.y = cvt2(f0.z, f0.w);
    hi.z = cvt2(f1.x, f1.y); hi.w = cvt2(f1.z, f1.w);
    *(uint4*)(bb + YHI_OFF + sw0) = hi;
    hi.x = cvt2(f2.x, f2.y); hi.y = cvt2(f2.z, f2.w);
    hi.z = cvt2(f3.x, f3.y); hi.w = cvt2(f3.z, f3.w);
    *(uint4*)(bb + YHI_OFF + sw1) = hi;
    return ss;
}

__global__ void k_nop() {}

// ---------------------------------------------------------------------------
// Pad-dtype detect (uint8-bool vs int32)
// ---------------------------------------------------------------------------
__global__ void __launch_bounds__(512) k_detect(const unsigned char* __restrict__ tp,
                                                const unsigned char* __restrict__ ip) {
    __shared__ int sflag;
    int tid = threadIdx.x;
    if (tid == 0) sflag = 0;
    __syncthreads();
    uint32_t acc = 0;
    const uint4* t4 = (const uint4*)tp;
    for (int i = tid; i < 2048; i += 512) {
        uint4 v = t4[i];
        acc |= (v.x | v.y | v.z | v.w) & 0xFFFFFF00u;
    }
    const uint4* i4 = (const uint4*)ip;
    for (int i = tid; i < 1600; i += 512) {
        uint4 v = i4[i];
        acc |= (v.x | v.y | v.z | v.w) & 0xFFFFFF00u;
    }
    uint32_t any = __ballot_sync(0xffffffffu, acc != 0);
    if ((tid & 31) == 0 && any) atomicOr(&sflag, 1);
    __syncthreads();
    if (tid == 0) g_isU8 = sflag;
}

// ---------------------------------------------------------------------------
// Warp-specialized full-batch GEMM (unchanged from R14): grid 256, 512 thr,
// 4-deep buffers, producers 8-15, consumers 0-7.
// ---------------------------------------------------------------------------
__global__ void __launch_bounds__(512, 1) k_gemm(const float* __restrict__ seq,
                                                 const unsigned char* __restrict__ tp,
                                                 const unsigned char* __restrict__ ip) {
    extern __shared__ __align__(16) char dsm[];
    __shared__ float pSq[928];
    __shared__ float sNxi[M], sNyi[NP];
    __shared__ float sXm[M], sYm[NP];

    const int b = blockIdx.x, tid = threadIdx.x;
    const int lane = tid & 31, w = tid >> 5;

    uint32_t rawb = smem_u32(dsm);
    uint32_t sb = (rawb + 1023u) & ~1023u;
    char* sbuf = dsm + (sb - rawb);

    const int u8 = g_isU8;
    if (tid < M) {
        int pad = u8 ? (tp[b * M + tid] != 0) : (((const int*)tp)[b * M + tid] != 0);
        sXm[tid] = pad ? 1e4f : 0.f;
    } else if (tid < M + NP) {
        int n = tid - M;
        int pad = (n >= NIMG) ? 1
                : (u8 ? (ip[b * NIMG + n] != 0) : (((const int*)ip)[b * NIMG + n] != 0));
        sYm[n] = pad ? 1e4f : 0.f;
    }
    __syncthreads();

    const float* seqb = seq + (size_t)b * 228 * D;

    if (w >= 8) {
        const int p = tid - 256;
        const int prow = p >> 2, pseg = p & 3;
        const float* px0 = seqb + (size_t)prow * D + pseg * 16;
        const float* px1 = px0 + (size_t)64 * D;
        const uint32_t xs00 = SWZ((uint32_t)(prow * 128 + pseg * 32));
        const uint32_t xs01 = SWZ((uint32_t)(prow * 128 + pseg * 32 + 16));
        const uint32_t xs10 = SWZ((uint32_t)((prow + 64) * 128 + pseg * 32));
        const uint32_t xs11 = SWZ((uint32_t)((prow + 64) * 128 + pseg * 32 + 16));
        const float* py0 = seqb + (size_t)(128 + prow) * D + pseg * 16;
        const int hasY1 = p < 144;
        const int zeroY1 = (p >= 144) && (p < 160);
        const float* py1 = py0 + (size_t)64 * D;
        const uint32_t ys00 = SWZ((uint32_t)(prow * 128 + pseg * 32));
        const uint32_t ys01 = SWZ((uint32_t)(prow * 128 + pseg * 32 + 16));
        const uint32_t ys10 = SWZ((uint32_t)((prow + 64) * 128 + pseg * 32));
        const uint32_t ys11 = SWZ((uint32_t)((prow + 64) * 128 + pseg * 32 + 16));

        if (zeroY1) {
            uint4 z = make_uint4(0u, 0u, 0u, 0u);
#pragma unroll
            for (int i = 0; i < NBUF; i++) {
                *(uint4*)(sbuf + i * BUF_BYTES + YHI_OFF + ys10) = z;
                *(uint4*)(sbuf + i * BUF_BYTES + YHI_OFF + ys11) = z;
            }
        }

        float nx0a = 0.f, nx1a = 0.f, ny0a = 0.f, ny1a = 0.f;
        for (int c = 0; c < 12; c++) {
            if (c >= NBUF) BAR_SYNC(5 + (c & 3));
            char* bb = sbuf + (uint32_t)(c & 3) * BUF_BYTES;
            const int co = c * 16;
            const float4* q;
            float4 x00, x01, x02, x03, x10, x11, x12, x13;
            float4 y00, y01, y02, y03, y10, y11, y12, y13;
            q = (const float4*)px0 + co; x00 = q[0]; x01 = q[1]; x02 = q[2]; x03 = q[3];
            q = (const float4*)px1 + co; x10 = q[0]; x11 = q[1]; x12 = q[2]; x13 = q[3];
            q = (const float4*)py0 + co; y00 = q[0]; y01 = q[1]; y02 = q[2]; y03 = q[3];
            if (hasY1) {
                q = (const float4*)py1 + co; y10 = q[0]; y11 = q[1]; y12 = q[2]; y13 = q[3];
            }
            nx0a += conv_store_xl(bb, xs00, xs01, x00, x01, x02, x03);
            nx1a += conv_store_xl(bb, xs10, xs11, x10, x11, x12, x13);
            ny0a += conv_store_yh(bb, ys00, ys01, y00, y01, y02, y03);
            if (hasY1)
                ny1a += conv_store_yh(bb, ys10, ys11, y10, y11, y12, y13);
            asm volatile("membar.cta;" ::: "memory");
            BAR_ARRIVE(1 + (c & 3));
        }
        pSq[p] = nx0a;
        pSq[p + 256] = nx1a;
        pSq[512 + p] = ny0a;
        if (p < 160) pSq[512 + p + 256] = ny1a;
        __syncthreads();
        if (tid - 256 < M) {
            int m = tid - 256;
            float ss = pSq[4 * m] + pSq[4 * m + 1] + pSq[4 * m + 2] + pSq[4 * m + 3];
            sNxi[m] = 1.f / fmaxf(sqrtf(ss), 1e-5f);
        }
        __syncthreads();
    } else {
        const int g = lane >> 2, q2 = lane & 3;
        const int j8 = lane >> 3, sub = lane & 7;
        const uint32_t arow_off = (uint32_t)((16 * w + ((j8 & 1) << 3) + sub) * 128);
        const int acol = (j8 >> 1) * 8;
        const int bcol = j8 * 8;

        float acc[52];
#pragma unroll
        for (int i = 0; i < 52; i++) acc[i] = 0.f;

        for (int c = 0; c < 12; c++) {
            BAR_SYNC(1 + (c & 3));
            uint32_t bbase = sb + (uint32_t)(c & 3) * BUF_BYTES;
#pragma unroll
            for (int k0 = 0; k0 < 64; k0 += 32) {
                uint32_t ah0[4], ah1[4], al0[4], al1[4];
                uint32_t offA0 = SWZ(arow_off + (uint32_t)((k0 + acol) * 2));
                uint32_t offA1 = SWZ(arow_off + (uint32_t)((k0 + 16 + acol) * 2));
                ldsm4(bbase + XHI_OFF + offA0, ah0);
                ldsm4(bbase + XHI_OFF + offA1, ah1);
                ldsm4(bbase + XLO_OFF + offA0, al0);
                ldsm4(bbase + XLO_OFF + offA1, al1);
#pragma unroll
                for (int t = 0; t < 13; t++) {
                    uint32_t offB = SWZ((uint32_t)((8 * t + sub) * 128 + (k0 + bcol) * 2));
                    uint32_t bh[4];
                    ldsm4(bbase + YHI_OFF + offB, bh);
                    float* d = &acc[t * 4];
                    mma_bf16(d, ah0, bh[0], bh[1]);
                    mma_bf16(d, al0, bh[0], bh[1]);
                    mma_bf16(d, ah1, bh[2], bh[3]);
                    mma_bf16(d, al1, bh[2], bh[3]);
                }
            }
            if (c < 12 - NBUF) BAR_ARRIVE(5 + (c & 3));
        }
        __syncthreads();
        if (tid < M + NP && tid >= M) {
            int n = tid - M;
            float ss = pSq[512 + 4 * n] + pSq[512 + 4 * n + 1]
                     + pSq[512 + 4 * n + 2] + pSq[512 + 4 * n + 3];
            sNyi[n] = 1.f / fmaxf(sqrtf(ss), 1e-5f);
        }
        __syncthreads();

        const int m0 = 16 * w + g, m1 = m0 + 8;
        const float xm0 = sXm[m0], xm1 = sXm[m1];
        const float nx0 = sNxi[m0], nx1 = sNxi[m1];
        float* gAout = g_A + ((size_t)(b * 8 + w) * 13) * 128;
#pragma unroll
        for (int t = 0; t < 13; t++) {
            int n0 = 8 * t + 2 * q2, n1 = n0 + 1;
            float ny0 = sNyi[n0], ny1 = sNyi[n1];
            float ym0 = sYm[n0],  ym1 = sYm[n1];
            float4 a;
            a.x = (xm0 > 0.f || ym0 > 0.f) ? 0.f
                : __expf(2.f * (acc[t * 4 + 0] * nx0 * ny0 - 1.f));
            a.y = (xm0 > 0.f || ym1 > 0.f) ? 0.f
                : __expf(2.f * (acc[t * 4 + 1] * nx0 * ny1 - 1.f));
            a.z = (xm1 > 0.f || ym0 > 0.f) ? 0.f
                : __expf(2.f * (acc[t * 4 + 2] * nx1 * ny0 - 1.f));
            a.w = (xm1 > 0.f || ym1 > 0.f) ? 0.f
                : __expf(2.f * (acc[t * 4 + 3] * nx1 * ny1 - 1.f));
            *(float4*)(gAout + t * 128 + lane * 4) = a;
        }
        return;
    }
}

// ---------------------------------------------------------------------------
// IPOT kernel R16: HYBRID A placement. Tiles 0-6 in registers (Ar[28]),
// tiles 7-12 in 24.6KB static smem (own-warp blob, conflict-free LDS.128).
// Qr[52] register-resident. No dl[] cache (reload sDelta, broadcast).
// Counted budget ~105-110 regs -> no spills at 2 CTAs/SM.
// ---------------------------------------------------------------------------
__global__ void __launch_bounds__(256, 2) k_ipot(const unsigned char* __restrict__ tp,
                                                 const unsigned char* __restrict__ ip) {
    __shared__ __align__(16) float sA6[8 * 6 * 128];   // tiles 7..12, 24.6KB
    __shared__ __align__(16) float sQP[NP * QP_STRIDE];
    __shared__ float sXm[M], sYm[NP];
    __shared__ __align__(8) float sDelta[NP];
    __shared__ float sRed[8];
    __shared__ int sCx, sCy;

    const int b = blockIdx.x, tid = threadIdx.x;
    const int lane = tid & 31, w = tid >> 5;
    const int g = lane >> 2, q2 = lane & 3;
    const int col = 8 * w + g;

    if (tid == 0) { sCx = 0; sCy = 0; }
    __syncthreads();
    const int u8 = g_isU8;
    if (tid < M) {
        int pad = u8 ? (tp[b * M + tid] != 0) : (((const int*)tp)[b * M + tid] != 0);
        sXm[tid] = pad ? 1e4f : 0.f;
        if (pad) atomicAdd(&sCx, 1);
    }
    if (tid < NP) {
        int pad = (tid >= NIMG) ? 1
                : (u8 ? (ip[b * NIMG + tid] != 0) : (((const int*)ip)[b * NIMG + tid] != 0));
        sYm[tid] = pad ? 1e4f : 0.f;
        if (pad && tid < NIMG) atomicAdd(&sCy, 1);
    }
    __syncthreads();

    // A blob: tiles 0-6 -> Ar regs; tiles 7-12 -> sA6 smem. Q init from both.
    float Ar[28], Qr[52];
    const float4* gA4 = (const float4*)(g_A + ((size_t)(b * 8 + w) * 13) * 128) + lane;
    float4* sA6w = (float4*)sA6 + w * 6 * 32 + lane;
#pragma unroll
    for (int t = 0; t < 7; t++) {
        float4 a = gA4[t * 32];
        Ar[t * 4 + 0] = a.x; Qr[t * 4 + 0] = a.x;
        Ar[t * 4 + 1] = a.y; Qr[t * 4 + 1] = a.y;
        Ar[t * 4 + 2] = a.z; Qr[t * 4 + 2] = a.z;
        Ar[t * 4 + 3] = a.w; Qr[t * 4 + 3] = a.w;
    }
#pragma unroll
    for (int t = 7; t < 13; t++) {
        float4 a = gA4[t * 32];
        sA6w[(t - 7) * 32] = a;
        Qr[t * 4 + 0] = a.x; Qr[t * 4 + 1] = a.y;
        Qr[t * 4 + 2] = a.z; Qr[t * 4 + 3] = a.w;
    }

    const int m0 = 16 * w + g;
    const float xm0 = sXm[m0], xm1 = sXm[m0 + 8];
    const float xl = (float)(M - sCx), yl = (float)(NIMG - sCy);

    float sig0 = xm0 > 0.f ? 0.f : 1.f / xl;
    float sig1 = xm1 > 0.f ? 0.f : 1.f / xl;

#pragma unroll
    for (int t = 0; t < 13; t++) {
        int n0 = 8 * t + 2 * q2;
        sQP[n0 * QP_STRIDE + col]       = Qr[t * 4 + 0] * sig0 + Qr[t * 4 + 2] * sig1;
        sQP[(n0 + 1) * QP_STRIDE + col] = Qr[t * 4 + 1] * sig0 + Qr[t * 4 + 3] * sig1;
    }
    __syncthreads();

    float ot = 0.f;
#pragma unroll 1
    for (int it = 0; it < ITERS; it++) {
        // delta[n]: sum 64 partials (16 LDS.128)
        if (tid < NP) {
            const float4* rp = (const float4*)&sQP[tid * QP_STRIDE];
            float4 r0 = rp[0], r1 = rp[1], r2 = rp[2], r3 = rp[3];
#pragma unroll
            for (int j = 4; j < 16; j += 4) {
                float4 v0 = rp[j], v1 = rp[j + 1], v2 = rp[j + 2], v3 = rp[j + 3];
                r0.x += v0.x; r0.y += v0.y; r0.z += v0.z; r0.w += v0.w;
                r1.x += v1.x; r1.y += v1.y; r1.z += v1.z; r1.w += v1.w;
                r2.x += v2.x; r2.y += v2.y; r2.z += v2.z; r2.w += v2.w;
                r3.x += v3.x; r3.y += v3.y; r3.z += v3.z; r3.w += v3.w;
            }
            float qs = (r0.x + r0.y + r0.z + r0.w) + (r1.x + r1.y + r1.z + r1.w)
                     + (r2.x + r2.y + r2.z + r2.w) + (r3.x + r3.y + r3.z + r3.w);
            sDelta[tid] = __fdividef(1.f, yl * qs + sYm[tid]);
        }
        __syncthreads();

        // r[m] = sum_n delta[n]*Q[n,m]; sigma warp-local (xor 1,2)
        float p0 = 0.f, p1 = 0.f;
#pragma unroll
        for (int t = 0; t < 13; t++) {
            float2 d = *(const float2*)&sDelta[8 * t + 2 * q2];
            p0 += d.x * Qr[t * 4 + 0] + d.y * Qr[t * 4 + 1];
            p1 += d.x * Qr[t * 4 + 2] + d.y * Qr[t * 4 + 3];
        }
        p0 += __shfl_xor_sync(0xffffffffu, p0, 1);
        p0 += __shfl_xor_sync(0xffffffffu, p0, 2);
        p1 += __shfl_xor_sync(0xffffffffu, p1, 1);
        p1 += __shfl_xor_sync(0xffffffffu, p1, 2);
        sig0 = __fdividef(1.f, xl * p0 + xm0);
        sig1 = __fdividef(1.f, xl * p1 + xm1);

        if (it < ITERS - 1) {
#pragma unroll
            for (int t = 0; t < 7; t++) {
                float2 d = *(const float2*)&sDelta[8 * t + 2 * q2];
                float q0 = Ar[t * 4 + 0] * Qr[t * 4 + 0] * (d.x * sig0);
                float q1 = Ar[t * 4 + 1] * Qr[t * 4 + 1] * (d.y * sig0);
                float q2v = Ar[t * 4 + 2] * Qr[t * 4 + 2] * (d.x * sig1);
                float q3 = Ar[t * 4 + 3] * Qr[t * 4 + 3] * (d.y * sig1);
                Qr[t * 4 + 0] = q0; Qr[t * 4 + 1] = q1;
                Qr[t * 4 + 2] = q2v; Qr[t * 4 + 3] = q3;
                int n0 = 8 * t + 2 * q2;
                sQP[n0 * QP_STRIDE + col]       = q0 * sig0 + q2v * sig1;
                sQP[(n0 + 1) * QP_STRIDE + col] = q1 * sig0 + q3 * sig1;
            }
#pragma unroll
            for (int t = 7; t < 13; t++) {
                float2 d = *(const float2*)&sDelta[8 * t + 2 * q2];
                float4 a = sA6w[(t - 7) * 32];
                float q0 = a.x * Qr[t * 4 + 0] * (d.x * sig0);
                float q1 = a.y * Qr[t * 4 + 1] * (d.y * sig0);
                float q2v = a.z * Qr[t * 4 + 2] * (d.x * sig1);
                float q3 = a.w * Qr[t * 4 + 3] * (d.y * sig1);
                Qr[t * 4 + 0] = q0; Qr[t * 4 + 1] = q1;
                Qr[t * 4 + 2] = q2v; Qr[t * 4 + 3] = q3;
                int n0 = 8 * t + 2 * q2;
                sQP[n0 * QP_STRIDE + col]       = q0 * sig0 + q2v * sig1;
                sQP[(n0 + 1) * QP_STRIDE + col] = q1 * sig0 + q3 * sig1;
            }
        } else {
#pragma unroll
            for (int t = 0; t < 7; t++) {
                float2 d = *(const float2*)&sDelta[8 * t + 2 * q2];
                float a0 = Ar[t * 4 + 0], a1 = Ar[t * 4 + 1];
                float a2 = Ar[t * 4 + 2], a3 = Ar[t * 4 + 3];
                if (a0 > 0.f) ot += (-0.5f * __logf(a0)) * Qr[t * 4 + 0] * d.x * sig0;
                if (a1 > 0.f) ot += (-0.5f * __logf(a1)) * Qr[t * 4 + 1] * d.y * sig0;
                if (a2 > 0.f) ot += (-0.5f * __logf(a2)) * Qr[t * 4 + 2] * d.x * sig1;
                if (a3 > 0.f) ot += (-0.5f * __logf(a3)) * Qr[t * 4 + 3] * d.y * sig1;
            }
#pragma unroll
            for (int t = 7; t < 13; t++) {
                float2 d = *(const float2*)&sDelta[8 * t + 2 * q2];
                float4 a = sA6w[(t - 7) * 32];
                if (a.x > 0.f) ot += (-0.5f * __logf(a.x)) * Qr[t * 4 + 0] * d.x * sig0;
                if (a.y > 0.f) ot += (-0.5f * __logf(a.y)) * Qr[t * 4 + 1] * d.y * sig0;
                if (a.z > 0.f) ot += (-0.5f * __logf(a.z)) * Qr[t * 4 + 2] * d.x * sig1;
                if (a.w > 0.f) ot += (-0.5f * __logf(a.w)) * Qr[t * 4 + 3] * d.y * sig1;
            }
        }
        __syncthreads();
    }

    ot += __shfl_xor_sync(0xffffffffu, ot, 16);
    ot += __shfl_xor_sync(0xffffffffu, ot, 8);
    ot += __shfl_xor_sync(0xffffffffu, ot, 4);
    ot += __shfl_xor_sync(0xffffffffu, ot, 2);
    ot += __shfl_xor_sync(0xffffffffu, ot, 1);
    if (lane == 0) sRed[w] = ot;
    __syncthreads();
    if (tid == 0) {
        float sum = 0.f;
#pragma unroll
        for (int ww = 0; ww < 8; ww++) sum += sRed[ww];
        g_ot[b] = sum;
    }
}

// ---------------------------------------------------------------------------
// Final signed batch reduction -> scalar loss.
// ---------------------------------------------------------------------------
__global__ void k_final(const int* __restrict__ isc, float* __restrict__ out) {
    int t = threadIdx.x;
    __shared__ float sRed[8];
    float v = g_ot[t];
    float s = (isc[t] == 1) ? v : -v;
    s += __shfl_xor_sync(0xffffffffu, s, 16);
    s += __shfl_xor_sync(0xffffffffu, s, 8);
    s += __shfl_xor_sync(0xffffffffu, s, 4);
    s += __shfl_xor_sync(0xffffffffu, s, 2);
    s += __shfl_xor_sync(0xffffffffu, s, 1);
    if ((t & 31) == 0) sRed[t >> 5] = s;
    __syncthreads();
    if (t == 0) {
        float tot = 0.f;
#pragma unroll
        for (int w = 0; w < 8; w++) tot += sRed[w];
        out[0] = tot / (float)BATCH;
    }
}

// ---------------------------------------------------------------------------
extern "C" void kernel_launch(void* const* d_in, const int* in_sizes, int n_in,
                              void* d_out, int out_size) {
    const float* seq = (const float*)d_in[0];
    const unsigned char* tp = (const unsigned char*)d_in[3];
    const unsigned char* ip = (const unsigned char*)d_in[4];
    const int* isc = (const int*)d_in[5];
    float* out = (float*)d_out;

    cudaFuncSetAttribute(k_gemm, cudaFuncAttributeMaxDynamicSharedMemorySize,
                         DSM_GEMM);

    k_detect<<<1, 512>>>(tp, ip);
    k_nop<<<1, 32>>>();   // spacer: k_ipot is profiled launch #4
    k_gemm<<<BATCH, 512, DSM_GEMM>>>(seq, tp, ip);
    k_ipot<<<BATCH, 256>>>(tp, ip);
    k_final<<<1, 256>>>(isc, out);
}

// round 17
// speedup vs baseline: 1.1618x; 1.0103x over previous
#include <cuda_runtime.h>
#include <cuda_bf16.h>
#include <stdint.h>

// Problem constants
#define BATCH 256
#define M 128
#define NIMG 100
#define NP 104          // 13 * 8
#define D 768
#define ITERS 50

// Full-batch GEMM staging (per buffer, swizzled bf16, 128B rows)
#define XHI_OFF 0u
#define XLO_OFF 16384u
#define YHI_OFF 32768u
#define BUF_BYTES 46080u
#define NBUF 4
#define DSM_GEMM (NBUF * 46080 + 1024)

#define QP_STRIDE 68    // 64 partial cols + 4 pad floats

#define SWZ(o) ((o) ^ (((o) >> 3) & 0x70))

#define BAR_SYNC(id)   asm volatile("bar.sync %0, 512;"   :: "r"(id) : "memory")
#define BAR_ARRIVE(id) asm volatile("bar.arrive %0, 512;" :: "r"(id) : "memory")

// A stored as fragment blob in ipot geometry:
// g_A[((b*8 + w)*13 + t)*128 + lane*4 + e]
__device__ __align__(16) float g_A[BATCH * 8 * 13 * 128];
__device__ float g_ot[BATCH];
__device__ int   g_isU8;

// ---------------------------------------------------------------------------
// Helpers
// ---------------------------------------------------------------------------
__device__ __forceinline__ uint32_t smem_u32(const void* p) {
    uint32_t a;
    asm("{ .reg .u64 t; cvta.to.shared.u64 t, %1; cvt.u32.u64 %0, t; }"
        : "=r"(a) : "l"(p));
    return a;
}
__device__ __forceinline__ void ldsm4(uint32_t addr, uint32_t* r) {
    asm volatile("ldmatrix.sync.aligned.m8n8.x4.shared.b16 {%0,%1,%2,%3}, [%4];"
                 : "=r"(r[0]), "=r"(r[1]), "=r"(r[2]), "=r"(r[3]) : "r"(addr));
}
__device__ __forceinline__ void mma_bf16(float* d, const uint32_t* a,
                                         uint32_t b0, uint32_t b1) {
    asm volatile(
        "mma.sync.aligned.m16n8k16.row.col.f32.bf16.bf16.f32 "
        "{%0,%1,%2,%3},{%4,%5,%6,%7},{%8,%9},{%0,%1,%2,%3};"
        : "+f"(d[0]), "+f"(d[1]), "+f"(d[2]), "+f"(d[3])
        : "r"(a[0]), "r"(a[1]), "r"(a[2]), "r"(a[3]), "r"(b0), "r"(b1));
}
__device__ __forceinline__ void split2(float a, float b, uint32_t& hi, uint32_t& lo) {
    asm("cvt.rn.bf16x2.f32 %0, %1, %2;" : "=r"(hi) : "f"(b), "f"(a));
    float ah = __uint_as_float(hi << 16);
    float bh = __uint_as_float(hi & 0xffff0000u);
    float la = a - ah, lb = b - bh;
    asm("cvt.rn.bf16x2.f32 %0, %1, %2;" : "=r"(lo) : "f"(lb), "f"(la));
}
__device__ __forceinline__ uint32_t cvt2(float a, float b) {
    uint32_t hi;
    asm("cvt.rn.bf16x2.f32 %0, %1, %2;" : "=r"(hi) : "f"(b), "f"(a));
    return hi;
}

__device__ __forceinline__ float conv_store_xl(char* bb, uint32_t sw0, uint32_t sw1,
                                               float4 f0, float4 f1,
                                               float4 f2, float4 f3) {
    float ss = f0.x*f0.x + f0.y*f0.y + f0.z*f0.z + f0.w*f0.w
             + f1.x*f1.x + f1.y*f1.y + f1.z*f1.z + f1.w*f1.w
             + f2.x*f2.x + f2.y*f2.y + f2.z*f2.z + f2.w*f2.w
             + f3.x*f3.x + f3.y*f3.y + f3.z*f3.z + f3.w*f3.w;
    uint4 hi, lo;
    split2(f0.x, f0.y, hi.x, lo.x);
    split2(f0.z, f0.w, hi.y, lo.y);
    split2(f1.x, f1.y, hi.z, lo.z);
    split2(f1.z, f1.w, hi.w, lo.w);
    *(uint4*)(bb + XHI_OFF + sw0) = hi;
    *(uint4*)(bb + XLO_OFF + sw0) = lo;
    split2(f2.x, f2.y, hi.x, lo.x);
    split2(f2.z, f2.w, hi.y, lo.y);
    split2(f3.x, f3.y, hi.z, lo.z);
    split2(f3.z, f3.w, hi.w, lo.w);
    *(uint4*)(bb + XHI_OFF + sw1) = hi;
    *(uint4*)(bb + XLO_OFF + sw1) = lo;
    return ss;
}
__device__ __forceinline__ float conv_store_yh(char* bb, uint32_t sw0, uint32_t sw1,
                                               float4 f0, float4 f1,
                                               float4 f2, float4 f3) {
    float ss = f0.x*f0.x + f0.y*f0.y + f0.z*f0.z + f0.w*f0.w
             + f1.x*f1.x + f1.y*f1.y + f1.z*f1.z + f1.w*f1.w
             + f2.x*f2.x + f2.y*f2.y + f2.z*f2.z + f2.w*f2.w
             + f3.x*f3.x + f3.y*f3.y + f3.z*f3.z + f3.w*f3.w;
    uint4 hi;
    hi.x = cvt2(f0.x, f0.y); hi.y = cvt2(f0.z, f0.w);
    hi.z = cvt2(f1.x, f1.y); hi.w = cvt2(f1.z, f1.w);
    *(uint4*)(bb + YHI_OFF + sw0) = hi;
    hi.x = cvt2(f2.x, f2.y); hi.y = cvt2(f2.z, f2.w);
    hi.z = cvt2(f3.x, f3.y); hi.w = cvt2(f3.z, f3.w);
    *(uint4*)(bb + YHI_OFF + sw1) = hi;
    return ss;
}

__global__ void k_nop() {}

// ---------------------------------------------------------------------------
// Pad-dtype detect (uint8-bool vs int32)
// ---------------------------------------------------------------------------
__global__ void __launch_bounds__(512) k_detect(const unsigned char* __restrict__ tp,
                                                const unsigned char* __restrict__ ip) {
    __shared__ int sflag;
    int tid = threadIdx.x;
    if (tid == 0) sflag = 0;
    __syncthreads();
    uint32_t acc = 0;
    const uint4* t4 = (const uint4*)tp;
    for (int i = tid; i < 2048; i += 512) {
        uint4 v = t4[i];
        acc |= (v.x | v.y | v.z | v.w) & 0xFFFFFF00u;
    }
    const uint4* i4 = (const uint4*)ip;
    for (int i = tid; i < 1600; i += 512) {
        uint4 v = i4[i];
        acc |= (v.x | v.y | v.z | v.w) & 0xFFFFFF00u;
    }
    uint32_t any = __ballot_sync(0xffffffffu, acc != 0);
    if ((tid & 31) == 0 && any) atomicOr(&sflag, 1);
    __syncthreads();
    if (tid == 0) g_isU8 = sflag;
}

// ---------------------------------------------------------------------------
// Warp-specialized full-batch GEMM with DATA-DEPENDENT WORK SKIPPING:
// rows/tiles that are fully masked (>= txt_len / img_len) skip loads,
// converts and mma. All threads still arrive at every barrier.
// Grid 256, 512 thr, 4-deep buffers, producers 8-15, consumers 0-7.
// ---------------------------------------------------------------------------
__global__ void __launch_bounds__(512, 1) k_gemm(const float* __restrict__ seq,
                                                 const unsigned char* __restrict__ tp,
                                                 const unsigned char* __restrict__ ip) {
    extern __shared__ __align__(16) char dsm[];
    __shared__ float pSq[928];
    __shared__ float sNxi[M], sNyi[NP];
    __shared__ float sXm[M], sYm[NP];
    __shared__ int sCx, sCy;

    const int b = blockIdx.x, tid = threadIdx.x;
    const int lane = tid & 31, w = tid >> 5;

    uint32_t rawb = smem_u32(dsm);
    uint32_t sb = (rawb + 1023u) & ~1023u;
    char* sbuf = dsm + (sb - rawb);

    if (tid == 0) { sCx = 0; sCy = 0; }
    __syncthreads();
    const int u8 = g_isU8;
    if (tid < M) {
        int pad = u8 ? (tp[b * M + tid] != 0) : (((const int*)tp)[b * M + tid] != 0);
        sXm[tid] = pad ? 1e4f : 0.f;
        if (pad) atomicAdd(&sCx, 1);
    } else if (tid < M + NP) {
        int n = tid - M;
        int pad = (n >= NIMG) ? 1
                : (u8 ? (ip[b * NIMG + n] != 0) : (((const int*)ip)[b * NIMG + n] != 0));
        sYm[n] = pad ? 1e4f : 0.f;
        if (pad && n < NIMG) atomicAdd(&sCy, 1);
    }
    __syncthreads();   // masks + counts visible
    const int xli = M - sCx;      // txt_len (>= 64)
    const int yli = NIMG - sCy;   // img_len (>= 50)

    const float* seqb = seq + (size_t)b * 228 * D;

    if (w >= 8) {
        // =============== PRODUCER warps ===============
        const int p = tid - 256;
        const int prow = p >> 2, pseg = p & 3;
        const float* px0 = seqb + (size_t)prow * D + pseg * 16;
        const float* px1 = px0 + (size_t)64 * D;
        const uint32_t xs00 = SWZ((uint32_t)(prow * 128 + pseg * 32));
        const uint32_t xs01 = SWZ((uint32_t)(prow * 128 + pseg * 32 + 16));
        const uint32_t xs10 = SWZ((uint32_t)((prow + 64) * 128 + pseg * 32));
        const uint32_t xs11 = SWZ((uint32_t)((prow + 64) * 128 + pseg * 32 + 16));
        const float* py0 = seqb + (size_t)(128 + prow) * D + pseg * 16;
        const int hasY1 = p < 144;
        const float* py1 = py0 + (size_t)64 * D;
        const uint32_t ys00 = SWZ((uint32_t)(prow * 128 + pseg * 32));
        const uint32_t ys01 = SWZ((uint32_t)(prow * 128 + pseg * 32 + 16));
        const uint32_t ys10 = SWZ((uint32_t)((prow + 64) * 128 + pseg * 32));
        const uint32_t ys11 = SWZ((uint32_t)((prow + 64) * 128 + pseg * 32 + 16));

        // activity predicates (X rows < 64 always active: txt_len >= 64)
        const int actX1 = (prow + 64) < xli;
        const int actY0 = prow < yli;
        const int actY1 = hasY1 && ((prow + 64) < yli);

        float nx0a = 0.f, nx1a = 0.f, ny0a = 0.f, ny1a = 0.f;
        for (int c = 0; c < 12; c++) {
            if (c >= NBUF) BAR_SYNC(5 + (c & 3));
            char* bb = sbuf + (uint32_t)(c & 3) * BUF_BYTES;
            const int co = c * 16;
            const float4* q;
            float4 x00, x01, x02, x03, x10, x11, x12, x13;
            float4 y00, y01, y02, y03, y10, y11, y12, y13;
            q = (const float4*)px0 + co; x00 = q[0]; x01 = q[1]; x02 = q[2]; x03 = q[3];
            if (actX1) {
                q = (const float4*)px1 + co; x10 = q[0]; x11 = q[1]; x12 = q[2]; x13 = q[3];
            }
            if (actY0) {
                q = (const float4*)py0 + co; y00 = q[0]; y01 = q[1]; y02 = q[2]; y03 = q[3];
            }
            if (actY1) {
                q = (const float4*)py1 + co; y10 = q[0]; y11 = q[1]; y12 = q[2]; y13 = q[3];
            }
            nx0a += conv_store_xl(bb, xs00, xs01, x00, x01, x02, x03);
            if (actX1)
                nx1a += conv_store_xl(bb, xs10, xs11, x10, x11, x12, x13);
            if (actY0)
                ny0a += conv_store_yh(bb, ys00, ys01, y00, y01, y02, y03);
            if (actY1)
                ny1a += conv_store_yh(bb, ys10, ys11, y10, y11, y12, y13);
            asm volatile("membar.cta;" ::: "memory");
            BAR_ARRIVE(1 + (c & 3));
        }
        pSq[p] = nx0a;
        pSq[p + 256] = nx1a;
        pSq[512 + p] = ny0a;
        if (p < 160) pSq[512 + p + 256] = ny1a;
        __syncthreads();
        if (tid - 256 < M) {
            int m = tid - 256;
            float ss = pSq[4 * m] + pSq[4 * m + 1] + pSq[4 * m + 2] + pSq[4 * m + 3];
            sNxi[m] = 1.f / fmaxf(sqrtf(ss), 1e-5f);
        }
        __syncthreads();
    } else {
        // =============== CONSUMER warps ===============
        const int g = lane >> 2, q2 = lane & 3;
        const int j8 = lane >> 3, sub = lane & 7;
        const uint32_t arow_off = (uint32_t)((16 * w + ((j8 & 1) << 3) + sub) * 128);
        const int acol = (j8 >> 1) * 8;
        const int bcol = j8 * 8;

        const int wact = (16 * w) < xli;          // warp row-group active
        const int nta = (yli + 7) >> 3;           // active n-tiles (>= 7)

        float acc[52];
#pragma unroll
        for (int i = 0; i < 52; i++) acc[i] = 0.f;

        for (int c = 0; c < 12; c++) {
            BAR_SYNC(1 + (c & 3));
            if (wact) {
                uint32_t bbase = sb + (uint32_t)(c & 3) * BUF_BYTES;
#pragma unroll
                for (int k0 = 0; k0 < 64; k0 += 32) {
                    uint32_t ah0[4], ah1[4], al0[4], al1[4];
                    uint32_t offA0 = SWZ(arow_off + (uint32_t)((k0 + acol) * 2));
                    uint32_t offA1 = SWZ(arow_off + (uint32_t)((k0 + 16 + acol) * 2));
                    ldsm4(bbase + XHI_OFF + offA0, ah0);
                    ldsm4(bbase + XHI_OFF + offA1, ah1);
                    ldsm4(bbase + XLO_OFF + offA0, al0);
                    ldsm4(bbase + XLO_OFF + offA1, al1);
#pragma unroll
                    for (int t = 0; t < 13; t++) {
                        if (t < nta) {
                            uint32_t offB = SWZ((uint32_t)((8 * t + sub) * 128 + (k0 + bcol) * 2));
                            uint32_t bh[4];
                            ldsm4(bbase + YHI_OFF + offB, bh);
                            float* d = &acc[t * 4];
                            mma_bf16(d, ah0, bh[0], bh[1]);
                            mma_bf16(d, al0, bh[0], bh[1]);
                            mma_bf16(d, ah1, bh[2], bh[3]);
                            mma_bf16(d, al1, bh[2], bh[3]);
                        }
                    }
                }
            }
            if (c < 12 - NBUF) BAR_ARRIVE(5 + (c & 3));
        }
        __syncthreads();
        if (tid < M + NP && tid >= M) {
            int n = tid - M;
            float ss = pSq[512 + 4 * n] + pSq[512 + 4 * n + 1]
                     + pSq[512 + 4 * n + 2] + pSq[512 + 4 * n + 3];
            sNyi[n] = 1.f / fmaxf(sqrtf(ss), 1e-5f);
        }
        __syncthreads();

        const int m0 = 16 * w + g, m1 = m0 + 8;
        const float xm0 = sXm[m0], xm1 = sXm[m1];
        const float nx0 = sNxi[m0], nx1 = sNxi[m1];
        float* gAout = g_A + ((size_t)(b * 8 + w) * 13) * 128;
#pragma unroll
        for (int t = 0; t < 13; t++) {
            int n0 = 8 * t + 2 * q2, n1 = n0 + 1;
            float ny0 = sNyi[n0], ny1 = sNyi[n1];
            float ym0 = sYm[n0],  ym1 = sYm[n1];
            float4 a;
            a.x = (xm0 > 0.f || ym0 > 0.f) ? 0.f
                : __expf(2.f * (acc[t * 4 + 0] * nx0 * ny0 - 1.f));
            a.y = (xm0 > 0.f || ym1 > 0.f) ? 0.f
                : __expf(2.f * (acc[t * 4 + 1] * nx0 * ny1 - 1.f));
            a.z = (xm1 > 0.f || ym0 > 0.f) ? 0.f
                : __expf(2.f * (acc[t * 4 + 2] * nx1 * ny0 - 1.f));
            a.w = (xm1 > 0.f || ym1 > 0.f) ? 0.f
                : __expf(2.f * (acc[t * 4 + 3] * nx1 * ny1 - 1.f));
            *(float4*)(gAout + t * 128 + lane * 4) = a;
        }
        return;
    }
}

// ---------------------------------------------------------------------------
// IPOT kernel (unchanged from R16): hybrid A placement (7 tiles regs +
// 6 tiles smem), Qr[52] regs, smem-partial qs, 2 CTAs/SM.
// ---------------------------------------------------------------------------
__global__ void __launch_bounds__(256, 2) k_ipot(const unsigned char* __restrict__ tp,
                                                 const unsigned char* __restrict__ ip) {
    __shared__ __align__(16) float sA6[8 * 6 * 128];
    __shared__ __align__(16) float sQP[NP * QP_STRIDE];
    __shared__ float sXm[M], sYm[NP];
    __shared__ __align__(8) float sDelta[NP];
    __shared__ float sRed[8];
    __shared__ int sCx, sCy;

    const int b = blockIdx.x, tid = threadIdx.x;
    const int lane = tid & 31, w = tid >> 5;
    const int g = lane >> 2, q2 = lane & 3;
    const int col = 8 * w + g;

    if (tid == 0) { sCx = 0; sCy = 0; }
    __syncthreads();
    const int u8 = g_isU8;
    if (tid < M) {
        int pad = u8 ? (tp[b * M + tid] != 0) : (((const int*)tp)[b * M + tid] != 0);
        sXm[tid] = pad ? 1e4f : 0.f;
        if (pad) atomicAdd(&sCx, 1);
    }
    if (tid < NP) {
        int pad = (tid >= NIMG) ? 1
                : (u8 ? (ip[b * NIMG + tid] != 0) : (((const int*)ip)[b * NIMG + tid] != 0));
        sYm[tid] = pad ? 1e4f : 0.f;
        if (pad && tid < NIMG) atomicAdd(&sCy, 1);
    }
    __syncthreads();

    float Ar[28], Qr[52];
    const float4* gA4 = (const float4*)(g_A + ((size_t)(b * 8 + w) * 13) * 128) + lane;
    float4* sA6w = (float4*)sA6 + w * 6 * 32 + lane;
#pragma unroll
    for (int t = 0; t < 7; t++) {
        float4 a = gA4[t * 32];
        Ar[t * 4 + 0] = a.x; Qr[t * 4 + 0] = a.x;
        Ar[t * 4 + 1] = a.y; Qr[t * 4 + 1] = a.y;
        Ar[t * 4 + 2] = a.z; Qr[t * 4 + 2] = a.z;
        Ar[t * 4 + 3] = a.w; Qr[t * 4 + 3] = a.w;
    }
#pragma unroll
    for (int t = 7; t < 13; t++) {
        float4 a = gA4[t * 32];
        sA6w[(t - 7) * 32] = a;
        Qr[t * 4 + 0] = a.x; Qr[t * 4 + 1] = a.y;
        Qr[t * 4 + 2] = a.z; Qr[t * 4 + 3] = a.w;
    }

    const int m0 = 16 * w + g;
    const float xm0 = sXm[m0], xm1 = sXm[m0 + 8];
    const float xl = (float)(M - sCx), yl = (float)(NIMG - sCy);

    float sig0 = xm0 > 0.f ? 0.f : 1.f / xl;
    float sig1 = xm1 > 0.f ? 0.f : 1.f / xl;

#pragma unroll
    for (int t = 0; t < 13; t++) {
        int n0 = 8 * t + 2 * q2;
        sQP[n0 * QP_STRIDE + col]       = Qr[t * 4 + 0] * sig0 + Qr[t * 4 + 2] * sig1;
        sQP[(n0 + 1) * QP_STRIDE + col] = Qr[t * 4 + 1] * sig0 + Qr[t * 4 + 3] * sig1;
    }
    __syncthreads();

    float ot = 0.f;
#pragma unroll 1
    for (int it = 0; it < ITERS; it++) {
        if (tid < NP) {
            const float4* rp = (const float4*)&sQP[tid * QP_STRIDE];
            float4 r0 = rp[0], r1 = rp[1], r2 = rp[2], r3 = rp[3];
#pragma unroll
            for (int j = 4; j < 16; j += 4) {
                float4 v0 = rp[j], v1 = rp[j + 1], v2 = rp[j + 2], v3 = rp[j + 3];
                r0.x += v0.x; r0.y += v0.y; r0.z += v0.z; r0.w += v0.w;
                r1.x += v1.x; r1.y += v1.y; r1.z += v1.z; r1.w += v1.w;
                r2.x += v2.x; r2.y += v2.y; r2.z += v2.z; r2.w += v2.w;
                r3.x += v3.x; r3.y += v3.y; r3.z += v3.z; r3.w += v3.w;
            }
            float qs = (r0.x + r0.y + r0.z + r0.w) + (r1.x + r1.y + r1.z + r1.w)
                     + (r2.x + r2.y + r2.z + r2.w) + (r3.x + r3.y + r3.z + r3.w);
            sDelta[tid] = __fdividef(1.f, yl * qs + sYm[tid]);
        }
        __syncthreads();

        float p0 = 0.f, p1 = 0.f;
#pragma unroll
        for (int t = 0; t < 13; t++) {
            float2 d = *(const float2*)&sDelta[8 * t + 2 * q2];
            p0 += d.x * Qr[t * 4 + 0] + d.y * Qr[t * 4 + 1];
            p1 += d.x * Qr[t * 4 + 2] + d.y * Qr[t * 4 + 3];
        }
        p0 += __shfl_xor_sync(0xffffffffu, p0, 1);
        p0 += __shfl_xor_sync(0xffffffffu, p0, 2);
        p1 += __shfl_xor_sync(0xffffffffu, p1, 1);
        p1 += __shfl_xor_sync(0xffffffffu, p1, 2);
        sig0 = __fdividef(1.f, xl * p0 + xm0);
        sig1 = __fdividef(1.f, xl * p1 + xm1);

        if (it < ITERS - 1) {
#pragma unroll
            for (int t = 0; t < 7; t++) {
                float2 d = *(const float2*)&sDelta[8 * t + 2 * q2];
                float q0 = Ar[t * 4 + 0] * Qr[t * 4 + 0] * (d.x * sig0);
                float q1 = Ar[t * 4 + 1] * Qr[t * 4 + 1] * (d.y * sig0);
                float q2v = Ar[t * 4 + 2] * Qr[t * 4 + 2] * (d.x * sig1);
                float q3 = Ar[t * 4 + 3] * Qr[t * 4 + 3] * (d.y * sig1);
                Qr[t * 4 + 0] = q0; Qr[t * 4 + 1] = q1;
                Qr[t * 4 + 2] = q2v; Qr[t * 4 + 3] = q3;
                int n0 = 8 * t + 2 * q2;
                sQP[n0 * QP_STRIDE + col]       = q0 * sig0 + q2v * sig1;
                sQP[(n0 + 1) * QP_STRIDE + col] = q1 * sig0 + q3 * sig1;
            }
#pragma unroll
            for (int t = 7; t < 13; t++) {
                float2 d = *(const float2*)&sDelta[8 * t + 2 * q2];
                float4 a = sA6w[(t - 7) * 32];
                float q0 = a.x * Qr[t * 4 + 0] * (d.x * sig0);
                float q1 = a.y * Qr[t * 4 + 1] * (d.y * sig0);
                float q2v = a.z * Qr[t * 4 + 2] * (d.x * sig1);
                float q3 = a.w * Qr[t * 4 + 3] * (d.y * sig1);
                Qr[t * 4 + 0] = q0; Qr[t * 4 + 1] = q1;
                Qr[t * 4 + 2] = q2v; Qr[t * 4 + 3] = q3;
                int n0 = 8 * t + 2 * q2;
                sQP[n0 * QP_STRIDE + col]       = q0 * sig0 + q2v * sig1;
                sQP[(n0 + 1) * QP_STRIDE + col] = q1 * sig0 + q3 * sig1;
            }
        } else {
#pragma unroll
            for (int t = 0; t < 7; t++) {
                float2 d = *(const float2*)&sDelta[8 * t + 2 * q2];
                float a0 = Ar[t * 4 + 0], a1 = Ar[t * 4 + 1];
                float a2 = Ar[t * 4 + 2], a3 = Ar[t * 4 + 3];
                if (a0 > 0.f) ot += (-0.5f * __logf(a0)) * Qr[t * 4 + 0] * d.x * sig0;
                if (a1 > 0.f) ot += (-0.5f * __logf(a1)) * Qr[t * 4 + 1] * d.y * sig0;
                if (a2 > 0.f) ot += (-0.5f * __logf(a2)) * Qr[t * 4 + 2] * d.x * sig1;
                if (a3 > 0.f) ot += (-0.5f * __logf(a3)) * Qr[t * 4 + 3] * d.y * sig1;
            }
#pragma unroll
            for (int t = 7; t < 13; t++) {
                float2 d = *(const float2*)&sDelta[8 * t + 2 * q2];
                float4 a = sA6w[(t - 7) * 32];
                if (a.x > 0.f) ot += (-0.5f * __logf(a.x)) * Qr[t * 4 + 0] * d.x * sig0;
                if (a.y > 0.f) ot += (-0.5f * __logf(a.y)) * Qr[t * 4 + 1] * d.y * sig0;
                if (a.z > 0.f) ot += (-0.5f * __logf(a.z)) * Qr[t * 4 + 2] * d.x * sig1;
                if (a.w > 0.f) ot += (-0.5f * __logf(a.w)) * Qr[t * 4 + 3] * d.y * sig1;
            }
        }
        __syncthreads();
    }

    ot += __shfl_xor_sync(0xffffffffu, ot, 16);
    ot += __shfl_xor_sync(0xffffffffu, ot, 8);
    ot += __shfl_xor_sync(0xffffffffu, ot, 4);
    ot += __shfl_xor_sync(0xffffffffu, ot, 2);
    ot += __shfl_xor_sync(0xffffffffu, ot, 1);
    if (lane == 0) sRed[w] = ot;
    __syncthreads();
    if (tid == 0) {
        float sum = 0.f;
#pragma unroll
        for (int ww = 0; ww < 8; ww++) sum += sRed[ww];
        g_ot[b] = sum;
    }
}

// ---------------------------------------------------------------------------
// Final signed batch reduction -> scalar loss.
// ---------------------------------------------------------------------------
__global__ void k_final(const int* __restrict__ isc, float* __restrict__ out) {
    int t = threadIdx.x;
    __shared__ float sRed[8];
    float v = g_ot[t];
    float s = (isc[t] == 1) ? v : -v;
    s += __shfl_xor_sync(0xffffffffu, s, 16);
    s += __shfl_xor_sync(0xffffffffu, s, 8);
    s += __shfl_xor_sync(0xffffffffu, s, 4);
    s += __shfl_xor_sync(0xffffffffu, s, 2);
    s += __shfl_xor_sync(0xffffffffu, s, 1);
    if ((t & 31) == 0) sRed[t >> 5] = s;
    __syncthreads();
    if (t == 0) {
        float tot = 0.f;
#pragma unroll
        for (int w = 0; w < 8; w++) tot += sRed[w];
        out[0] = tot / (float)BATCH;
    }
}

// ---------------------------------------------------------------------------
extern "C" void kernel_launch(void* const* d_in, const int* in_sizes, int n_in,
                              void* d_out, int out_size) {
    const float* seq = (const float*)d_in[0];
    const unsigned char* tp = (const unsigned char*)d_in[3];
    const unsigned char* ip = (const unsigned char*)d_in[4];
    const int* isc = (const int*)d_in[5];
    float* out = (float*)d_out;

    cudaFuncSetAttribute(k_gemm, cudaFuncAttributeMaxDynamicSharedMemorySize,
                         DSM_GEMM);

    k_detect<<<1, 512>>>(tp, ip);
    k_nop<<<1, 32>>>();
    k_nop<<<1, 32>>>();   // spacers: k_gemm is profiled launch #4
    k_gemm<<<BATCH, 512, DSM_GEMM>>>(seq, tp, ip);
    k_ipot<<<BATCH, 256>>>(tp, ip);
    k_final<<<1, 256>>>(isc, out);
}